// round 7
// baseline (speedup 1.0000x reference)
#include <cuda_runtime.h>
#include <math.h>
#include <string.h>

#define NPATH 11
#define DIMF  288
#define BZ    8
#define CHK   64
#define NT    128
#define UVS   8            // uv-split factor
#define CHPC  (16/UVS)     // chunks per CTA per path
#define X1S   289
#define X2S   288

#define FMA2(d,a,b) asm("fma.rn.f32x2 %0, %1, %2, %0;" : "+l"(d) : "l"(a), "l"(b))
#define MUL2(d,a,b) asm("mul.rn.f32x2 %0, %1, %2;" : "=l"(d) : "l"(a), "l"(b))
#define PK2(d,lo,hi) asm("mov.b64 %0, {%1, %2};" : "=l"(d) : "f"(lo), "f"(hi))
#define UPK2(lo,hi,s) asm("mov.b64 {%0, %1}, %2;" : "=f"(lo), "=f"(hi) : "l"(s))

static const int hc_l1[NPATH] = {0,1,2,0,1,1,2,0,1,2,2};
static const int hc_l2[NPATH] = {0,1,2,1,0,2,1,2,1,0,2};
static const int hc_lo[NPATH] = {0,0,0,1,1,1,1,2,2,2,2};

__device__ float g_C[NPATH][125];          // dense normalized w3j, [(i*D2+j)*K + k]
__device__ float g_part[UVS][2048*DIMF];   // scratch partials

// ---------------- host-side Wigner-3j (exact port of reference) ------------
static double hfact(int n){ double r=1.0; for(int i=2;i<=n;++i) r*=i; return r; }

static double h_su2(int j1,int m1,int j2,int m2,int j3,int m3){
  if (m1+m2 != m3) return 0.0;
  int vmin = -j1+j2+m3; if (-j1+m1 > vmin) vmin = -j1+m1; if (vmin < 0) vmin = 0;
  int vmax = j2+j3+m1; if (j3-j1+j2 < vmax) vmax = j3-j1+j2; if (j3+m3 < vmax) vmax = j3+m3;
  if (vmax < vmin) return 0.0;
  double C = sqrt((2.0*j3+1.0)
    * hfact(j3+j1-j2)*hfact(j3-j1+j2)*hfact(j1+j2-j3)*hfact(j3+m3)*hfact(j3-m3)
    / (hfact(j1+j2+j3+1)*hfact(j1-m1)*hfact(j1+m1)*hfact(j2-m2)*hfact(j2+m2)));
  double S = 0.0;
  for (int v = vmin; v <= vmax; ++v){
    double t = hfact(j2+j3+m1-v)*hfact(j1-m1+v)
             / (hfact(v)*hfact(j3-j1+j2-v)*hfact(j3+m3-v)*hfact(v+j1-j2-m3));
    S += ((v+j2+m2)&1) ? -t : t;
  }
  return C*S;
}

static void h_q(int l,int a,int b,double&re,double&im){
  double r=0.0,i=0.0; int m=a-l; const double s2=0.70710678118654752440;
  if (m<0){ if (b==l-m) r=s2; if (b==l+m) i=-s2; }
  else if (m==0){ if (b==l) r=1.0; }
  else { double s=(m&1)?-1.0:1.0; if (b==l+m) r=s*s2; if (b==l-m) i=s*s2; }
  if (l==1){ double t=r; r=i; i=-t; }       // *(-i)
  else if (l==2){ r=-r; i=-i; }             // *(-1)
  re=r; im=i;
}

static void compute_w3j_dense(float Cd[NPATH][125]){
  for (int p=0;p<NPATH;++p){
    int l1=hc_l1[p], l2=hc_l2[p], l3=hc_lo[p];
    int d1=2*l1+1, d2=2*l2+1, d3=2*l3+1;
    double cg[125]; for (int e=0;e<125;++e) cg[e]=0.0;
    for (int i=0;i<d1;++i) for (int k=0;k<d2;++k){
      int m1=i-l1, m2=k-l2;
      if (m1+m2 >= -l3 && m1+m2 <= l3)
        cg[(i*d2+k)*d3 + (l3+m1+m2)] = h_su2(l1,m1,l2,m2,l3,m1+m2);
    }
    double Cv[125]; double nrm=0.0;
    for (int jj=0;jj<d1;++jj) for (int ll=0;ll<d2;++ll) for (int mm=0;mm<d3;++mm){
      double cr=0.0;
      for (int i=0;i<d1;++i){
        double q1r,q1i; h_q(l1,i,jj,q1r,q1i);
        if (q1r==0.0 && q1i==0.0) continue;
        for (int k=0;k<d2;++k){
          double q2r,q2i; h_q(l2,k,ll,q2r,q2i);
          if (q2r==0.0 && q2i==0.0) continue;
          int n=(i-l1)+(k-l2)+l3;
          if (n<0 || n>=d3) continue;
          double g=cg[(i*d2+k)*d3+n];
          if (g==0.0) continue;
          double q3r,q3i; h_q(l3,n,mm,q3r,q3i); q3i=-q3i;
          double ar=q1r*q2r-q1i*q2i, ai=q1r*q2i+q1i*q2r;
          cr += g*(ar*q3r - ai*q3i);
        }
      }
      Cv[(jj*d2+ll)*d3+mm]=cr; nrm += cr*cr;
    }
    double inorm = 1.0/sqrt(nrm);
    for (int e=0;e<125;++e) Cd[p][e]=0.f;
    for (int e=0;e<d1*d2*d3;++e) Cd[p][e] = (float)(Cv[e]*inorm);
  }
}

// ------------------------- main kernel -------------------------------------
template<int L1, int L2, int LO>
__device__ __forceinline__ void process_path(
    int p, int ch0, const float* __restrict__ ws,
    const float* x1s, const float* x2t,
    float* wss, unsigned long long* Tp, unsigned long long* sC2,
    unsigned long long* acc, int tid)
{
  constexpr int D1 = 2*L1+1, D2 = 2*L2+1, K = 2*LO+1;
  constexpr int O1  = (L1==0)?0:((L1==1)?32:128);
  constexpr int O2T = (L2==0)?0:((L2==1)?32:128);
  constexpr int AO  = (LO==0)?0:((LO==1)?1:4);
  constexpr int NCF = D1*D2*K;
  constexpr int PASSES = (NCF > 64) ? 2 : 1;   // (2,2,2) split for regs
  constexpr int NPP = 2/PASSES;                // z-pairs per pass

  if (tid < NCF){
    float cf = g_C[p][tid];
    unsigned long long d; PK2(d, cf, cf);
    sC2[tid] = d;
  }
  const float* wsp = ws + (size_t)p * 32768;
  const int c   = tid & 63, zb  = tid >> 6;    // T-build mapping
  const int w   = tid & 31, zps = tid >> 5;    // sweep mapping

  for (int ch = ch0; ch < ch0 + CHPC; ++ch){
    __syncthreads();
    // stage weights [c][w] layout (conflict-free stores & loads)
    #pragma unroll
    for (int r = 0; r < 16; ++r){
      int e = r*128 + tid;
      wss[(e>>5)*33 + (e&31)] = __ldg(wsp + ch*2048 + e);
    }
    // ---- T build: z-pairs (zp, zp+4) packed in u64, f32x2 math ----
    {
      int uv = ch*CHK + c;
      int u = uv >> 5, v = uv & 31;
      #pragma unroll
      for (int ps = 0; ps < PASSES; ++ps){
        unsigned long long Ap[NPP][D1], Bp[NPP][D2], tP[NPP][K];
        #pragma unroll
        for (int q = 0; q < NPP; ++q){
          int zp = zb*2 + ps*NPP + q;
          #pragma unroll
          for (int i = 0; i < D1; ++i)
            PK2(Ap[q][i], x1s[zp*X1S + O1 + u*D1 + i],
                          x1s[(zp+4)*X1S + O1 + u*D1 + i]);
          #pragma unroll
          for (int j = 0; j < D2; ++j)
            PK2(Bp[q][j], x2t[zp*X2S + O2T + j*32 + v],
                          x2t[(zp+4)*X2S + O2T + j*32 + v]);
          #pragma unroll
          for (int k = 0; k < K; ++k) tP[q][k] = 0ull;
        }
        #pragma unroll
        for (int i = 0; i < D1; ++i){
          #pragma unroll
          for (int j = 0; j < D2; ++j){
            unsigned long long pp[NPP];
            #pragma unroll
            for (int q = 0; q < NPP; ++q) MUL2(pp[q], Ap[q][i], Bp[q][j]);
            #pragma unroll
            for (int k = 0; k < K; ++k){
              unsigned long long cf = sC2[(i*D2+j)*K + k];
              #pragma unroll
              for (int q = 0; q < NPP; ++q) FMA2(tP[q][k], cf, pp[q]);
            }
          }
        }
        #pragma unroll
        for (int q = 0; q < NPP; ++q){
          int zp = zb*2 + ps*NPP + q;
          #pragma unroll
          for (int k = 0; k < K; ++k)
            Tp[(zp*K + k)*CHK + c] = tP[q][k];
        }
      }
    }
    __syncthreads();
    // ---- sweep: thread owns (w, z-pair zps); u64 pair accumulators ----
    #pragma unroll
    for (int c4 = 0; c4 < 16; ++c4){
      float wv0 = wss[(c4*4+0)*33 + w];
      float wv1 = wss[(c4*4+1)*33 + w];
      float wv2 = wss[(c4*4+2)*33 + w];
      float wv3 = wss[(c4*4+3)*33 + w];
      unsigned long long wp0,wp1,wp2,wp3;
      PK2(wp0,wv0,wv0); PK2(wp1,wv1,wv1); PK2(wp2,wv2,wv2); PK2(wp3,wv3,wv3);
      #pragma unroll
      for (int k = 0; k < K; ++k){
        const ulonglong2* tb = (const ulonglong2*)(Tp + (zps*K + k)*CHK + c4*4);
        ulonglong2 tA = tb[0];
        ulonglong2 tB = tb[1];
        FMA2(acc[AO+k], wp0, tA.x);
        FMA2(acc[AO+k], wp1, tA.y);
        FMA2(acc[AO+k], wp2, tB.x);
        FMA2(acc[AO+k], wp3, tB.y);
      }
    }
  }
}

__global__ void __launch_bounds__(NT, 5) tp_kernel(
    const float* __restrict__ x1, const float* __restrict__ x2,
    const float* __restrict__ ws)
{
  __shared__ float x1s[BZ*X1S];
  __shared__ float x2t[BZ*X2S];
  __shared__ float wss[64*33];
  __shared__ unsigned long long Tp [4*5*CHK];   // z-pairs x K x c
  __shared__ unsigned long long sC2[125];

  int tid  = threadIdx.x;
  int bid  = blockIdx.x;
  int half = bid & (UVS-1);
  int ch0  = half * CHPC;
  int zbase = (bid >> 3) * BZ;

  for (int e = tid; e < BZ*DIMF; e += NT){
    int z = e / DIMF, c = e - z*DIMF;
    x1s[z*X1S + c] = x1[(size_t)(zbase+z)*DIMF + c];
    float v2 = x2[(size_t)(zbase+z)*DIMF + c];
    int dst;
    if (c < 32) dst = c;
    else if (c < 128){ int idx = c - 32;  dst = 32  + (idx % 3)*32 + idx/3; }
    else             { int idx = c - 128; dst = 128 + (idx % 5)*32 + idx/5; }
    x2t[z*X2S + dst] = v2;
  }

  unsigned long long acc[9];
  #pragma unroll
  for (int i = 0; i < 9; ++i) acc[i] = 0ull;

  process_path<0,0,0>( 0, ch0, ws, x1s,x2t, wss,Tp,sC2, acc, tid);
  process_path<1,1,0>( 1, ch0, ws, x1s,x2t, wss,Tp,sC2, acc, tid);
  process_path<2,2,0>( 2, ch0, ws, x1s,x2t, wss,Tp,sC2, acc, tid);
  process_path<0,1,1>( 3, ch0, ws, x1s,x2t, wss,Tp,sC2, acc, tid);
  process_path<1,0,1>( 4, ch0, ws, x1s,x2t, wss,Tp,sC2, acc, tid);
  process_path<1,2,1>( 5, ch0, ws, x1s,x2t, wss,Tp,sC2, acc, tid);
  process_path<2,1,1>( 6, ch0, ws, x1s,x2t, wss,Tp,sC2, acc, tid);
  process_path<0,2,2>( 7, ch0, ws, x1s,x2t, wss,Tp,sC2, acc, tid);
  process_path<1,1,2>( 8, ch0, ws, x1s,x2t, wss,Tp,sC2, acc, tid);
  process_path<2,0,2>( 9, ch0, ws, x1s,x2t, wss,Tp,sC2, acc, tid);
  process_path<2,2,2>(10, ch0, ws, x1s,x2t, wss,Tp,sC2, acc, tid);

  const float A0f = 0.01804219591217583f;   // sqrt(1/3072)
  const float A1f = 0.02706329386826371f;   // sqrt(3)/64
  const float A2f = 0.03493856214843422f;   // sqrt(5)/64

  int w   = tid & 31;
  int zps = tid >> 5;
  float* o0 = g_part[half] + (size_t)(zbase + zps) * DIMF;
  float* o1 = g_part[half] + (size_t)(zbase + zps + 4) * DIMF;
  float lo, hi;
  UPK2(lo, hi, acc[0]);
  o0[w] = A0f * lo;  o1[w] = A0f * hi;
  #pragma unroll
  for (int k = 0; k < 3; ++k){
    UPK2(lo, hi, acc[1+k]);
    o0[32 + w*3 + k] = A1f * lo;
    o1[32 + w*3 + k] = A1f * hi;
  }
  #pragma unroll
  for (int k = 0; k < 5; ++k){
    UPK2(lo, hi, acc[4+k]);
    o0[128 + w*5 + k] = A2f * lo;
    o1[128 + w*5 + k] = A2f * hi;
  }
}

__global__ void reduce_kernel(float* __restrict__ out){
  int i = blockIdx.x * blockDim.x + threadIdx.x;
  float4 r = make_float4(0.f, 0.f, 0.f, 0.f);
  #pragma unroll
  for (int s = 0; s < UVS; ++s){
    float4 a = ((const float4*)g_part[s])[i];
    r.x += a.x; r.y += a.y; r.z += a.z; r.w += a.w;
  }
  ((float4*)out)[i] = r;
}

extern "C" void kernel_launch(void* const* d_in, const int* in_sizes, int n_in,
                              void* d_out, int out_size) {
  const float* x1 = (const float*)d_in[0];
  const float* x2 = (const float*)d_in[1];
  const float* ws = (const float*)d_in[2];
  float* out = (float*)d_out;
  (void)in_sizes; (void)n_in; (void)out_size;

  static float h_C[NPATH][125];
  compute_w3j_dense(h_C);
  cudaMemcpyToSymbolAsync(g_C, h_C, sizeof(h_C), 0, cudaMemcpyHostToDevice, 0);

  tp_kernel<<<(2048/BZ)*UVS, NT>>>(x1, x2, ws);
  reduce_kernel<<<(2048*DIMF/4)/256, 256>>>(out);
}

// round 8
// speedup vs baseline: 1.2244x; 1.2244x over previous
#include <cuda_runtime.h>
#include <math.h>
#include <string.h>

#define NPATH 11
#define DIMF  288
#define BZ    8
#define CHK   64
#define NT    128
#define UVS   8            // uv-split factor
#define CHPC  (16/UVS)     // chunks per CTA per path
#define X1S   289
#define X2S   288
#define TSTR  72           // padded T row stride (banks: 8K mod 32 != 0)

static const int hc_l1[NPATH] = {0,1,2,0,1,1,2,0,1,2,2};
static const int hc_l2[NPATH] = {0,1,2,1,0,2,1,2,1,0,2};
static const int hc_lo[NPATH] = {0,0,0,1,1,1,1,2,2,2,2};

__device__ float g_C[NPATH][125];          // dense normalized w3j, [(i*D2+j)*K + k]
__device__ float g_part[UVS][2048*DIMF];   // scratch partials

// ---------------- host-side Wigner-3j (exact port of reference) ------------
static double hfact(int n){ double r=1.0; for(int i=2;i<=n;++i) r*=i; return r; }

static double h_su2(int j1,int m1,int j2,int m2,int j3,int m3){
  if (m1+m2 != m3) return 0.0;
  int vmin = -j1+j2+m3; if (-j1+m1 > vmin) vmin = -j1+m1; if (vmin < 0) vmin = 0;
  int vmax = j2+j3+m1; if (j3-j1+j2 < vmax) vmax = j3-j1+j2; if (j3+m3 < vmax) vmax = j3+m3;
  if (vmax < vmin) return 0.0;
  double C = sqrt((2.0*j3+1.0)
    * hfact(j3+j1-j2)*hfact(j3-j1+j2)*hfact(j1+j2-j3)*hfact(j3+m3)*hfact(j3-m3)
    / (hfact(j1+j2+j3+1)*hfact(j1-m1)*hfact(j1+m1)*hfact(j2-m2)*hfact(j2+m2)));
  double S = 0.0;
  for (int v = vmin; v <= vmax; ++v){
    double t = hfact(j2+j3+m1-v)*hfact(j1-m1+v)
             / (hfact(v)*hfact(j3-j1+j2-v)*hfact(j3+m3-v)*hfact(v+j1-j2-m3));
    S += ((v+j2+m2)&1) ? -t : t;
  }
  return C*S;
}

static void h_q(int l,int a,int b,double&re,double&im){
  double r=0.0,i=0.0; int m=a-l; const double s2=0.70710678118654752440;
  if (m<0){ if (b==l-m) r=s2; if (b==l+m) i=-s2; }
  else if (m==0){ if (b==l) r=1.0; }
  else { double s=(m&1)?-1.0:1.0; if (b==l+m) r=s*s2; if (b==l-m) i=s*s2; }
  if (l==1){ double t=r; r=i; i=-t; }       // *(-i)
  else if (l==2){ r=-r; i=-i; }             // *(-1)
  re=r; im=i;
}

static void compute_w3j_dense(float Cd[NPATH][125]){
  for (int p=0;p<NPATH;++p){
    int l1=hc_l1[p], l2=hc_l2[p], l3=hc_lo[p];
    int d1=2*l1+1, d2=2*l2+1, d3=2*l3+1;
    double cg[125]; for (int e=0;e<125;++e) cg[e]=0.0;
    for (int i=0;i<d1;++i) for (int k=0;k<d2;++k){
      int m1=i-l1, m2=k-l2;
      if (m1+m2 >= -l3 && m1+m2 <= l3)
        cg[(i*d2+k)*d3 + (l3+m1+m2)] = h_su2(l1,m1,l2,m2,l3,m1+m2);
    }
    double Cv[125]; double nrm=0.0;
    for (int jj=0;jj<d1;++jj) for (int ll=0;ll<d2;++ll) for (int mm=0;mm<d3;++mm){
      double cr=0.0;
      for (int i=0;i<d1;++i){
        double q1r,q1i; h_q(l1,i,jj,q1r,q1i);
        if (q1r==0.0 && q1i==0.0) continue;
        for (int k=0;k<d2;++k){
          double q2r,q2i; h_q(l2,k,ll,q2r,q2i);
          if (q2r==0.0 && q2i==0.0) continue;
          int n=(i-l1)+(k-l2)+l3;
          if (n<0 || n>=d3) continue;
          double g=cg[(i*d2+k)*d3+n];
          if (g==0.0) continue;
          double q3r,q3i; h_q(l3,n,mm,q3r,q3i); q3i=-q3i;
          double ar=q1r*q2r-q1i*q2i, ai=q1r*q2i+q1i*q2r;
          cr += g*(ar*q3r - ai*q3i);
        }
      }
      Cv[(jj*d2+ll)*d3+mm]=cr; nrm += cr*cr;
    }
    double inorm = 1.0/sqrt(nrm);
    for (int e=0;e<125;++e) Cd[p][e]=0.f;
    for (int e=0;e<d1*d2*d3;++e) Cd[p][e] = (float)(Cv[e]*inorm);
  }
}

// ------------------------- main kernel -------------------------------------
template<int L1, int L2, int LO>
__device__ __forceinline__ void process_path(
    int p, int ch0, const float* __restrict__ ws,
    const float* x1s, const float* x2t,
    float* wss, float* Ts, float* sC,
    float* acc0, float* acc1, int tid, int wt, int zs)
{
  constexpr int D1 = 2*L1+1, D2 = 2*L2+1, K = 2*LO+1;
  constexpr int O1  = (L1==0)?0:((L1==1)?32:128);
  constexpr int O2T = (L2==0)?0:((L2==1)?32:128);
  constexpr int AO  = (LO==0)?0:((LO==1)?1:4);

  for (int e = tid; e < K*D1*D2; e += NT) sC[e] = g_C[p][e];
  const float* wsp = ws + (size_t)p * 32768;

  for (int ch = ch0; ch < ch0 + CHPC; ++ch){
    __syncthreads();
    // prefetch weights into registers (hide L2 latency under T-build)
    float wreg[16];
    #pragma unroll
    for (int r = 0; r < 16; ++r)
      wreg[r] = __ldg(wsp + ch*2048 + r*128 + tid);

    // dense unrolled T-build: thread owns (c, z-base), 2 z per pass, 2 passes
    {
      int c  = tid & 63;
      int zb = tid >> 6;            // 0 or 1
      int uv = ch*CHK + c;
      int u  = uv >> 5, v = uv & 31;
      #pragma unroll
      for (int rp = 0; rp < 2; ++rp){
        int za = zb + rp*4;
        int zc = za + 2;
        float A0[D1], A1[D1], B0[D2], B1[D2];
        #pragma unroll
        for (int i = 0; i < D1; ++i){
          A0[i] = x1s[za*X1S + O1 + u*D1 + i];
          A1[i] = x1s[zc*X1S + O1 + u*D1 + i];
        }
        #pragma unroll
        for (int j = 0; j < D2; ++j){
          B0[j] = x2t[za*X2S + O2T + j*32 + v];
          B1[j] = x2t[zc*X2S + O2T + j*32 + v];
        }
        float t0[K], t1[K];
        #pragma unroll
        for (int k = 0; k < K; ++k){ t0[k]=0.f; t1[k]=0.f; }
        #pragma unroll
        for (int i = 0; i < D1; ++i){
          #pragma unroll
          for (int j = 0; j < D2; ++j){
            float p0 = A0[i]*B0[j];
            float p1 = A1[i]*B1[j];
            #pragma unroll
            for (int k = 0; k < K; ++k){
              float cf = sC[(i*D2+j)*K + k];
              t0[k] = fmaf(cf, p0, t0[k]);
              t1[k] = fmaf(cf, p1, t1[k]);
            }
          }
        }
        #pragma unroll
        for (int k = 0; k < K; ++k){
          Ts[(za*K + k)*TSTR + c] = t0[k];
          Ts[(zc*K + k)*TSTR + c] = t1[k];
        }
      }
    }
    // store weights NATURAL [c][w] layout: coalesced, conflict-free
    #pragma unroll
    for (int r = 0; r < 16; ++r)
      wss[r*128 + tid] = wreg[r];
    __syncthreads();
    // sweep: weights scalar broadcast (bank = wt, conflict-free), T via float4
    #pragma unroll 4
    for (int c4 = 0; c4 < CHK/4; ++c4){
      float wa0 = wss[(c4*4+0)*32 + wt],      wa1 = wss[(c4*4+1)*32 + wt];
      float wa2 = wss[(c4*4+2)*32 + wt],      wa3 = wss[(c4*4+3)*32 + wt];
      float wb0 = wss[(c4*4+0)*32 + wt + 16], wb1 = wss[(c4*4+1)*32 + wt + 16];
      float wb2 = wss[(c4*4+2)*32 + wt + 16], wb3 = wss[(c4*4+3)*32 + wt + 16];
      #pragma unroll
      for (int k = 0; k < K; ++k){
        float4 t = *(const float4*)(Ts + (zs*K + k)*TSTR + c4*4);
        acc0[AO+k] = fmaf(wa0, t.x, fmaf(wa1, t.y, fmaf(wa2, t.z, fmaf(wa3, t.w, acc0[AO+k]))));
        acc1[AO+k] = fmaf(wb0, t.x, fmaf(wb1, t.y, fmaf(wb2, t.z, fmaf(wb3, t.w, acc1[AO+k]))));
      }
    }
  }
}

__global__ void __launch_bounds__(NT, 5) tp_kernel(
    const float* __restrict__ x1, const float* __restrict__ x2,
    const float* __restrict__ ws)
{
  __shared__ float x1s[BZ*X1S];
  __shared__ float x2t[BZ*X2S];
  __shared__ float wss[64*32];
  __shared__ float Ts [BZ*5*TSTR];
  __shared__ float sC [125];

  int tid  = threadIdx.x;
  int wt   = tid & 15;
  int zs   = tid >> 4;
  int bid  = blockIdx.x;
  int half = bid & (UVS-1);
  int ch0  = half * CHPC;
  int zbase = (bid >> 3) * BZ;

  for (int e = tid; e < BZ*DIMF; e += NT){
    int z = e / DIMF, c = e - z*DIMF;
    x1s[z*X1S + c] = x1[(size_t)(zbase+z)*DIMF + c];
    float v2 = x2[(size_t)(zbase+z)*DIMF + c];
    int dst;
    if (c < 32) dst = c;
    else if (c < 128){ int idx = c - 32;  dst = 32  + (idx % 3)*32 + idx/3; }
    else             { int idx = c - 128; dst = 128 + (idx % 5)*32 + idx/5; }
    x2t[z*X2S + dst] = v2;
  }

  float acc0[9], acc1[9];
  #pragma unroll
  for (int i = 0; i < 9; ++i){ acc0[i]=0.f; acc1[i]=0.f; }

  process_path<0,0,0>( 0, ch0, ws, x1s,x2t, wss,Ts,sC, acc0,acc1, tid,wt,zs);
  process_path<1,1,0>( 1, ch0, ws, x1s,x2t, wss,Ts,sC, acc0,acc1, tid,wt,zs);
  process_path<2,2,0>( 2, ch0, ws, x1s,x2t, wss,Ts,sC, acc0,acc1, tid,wt,zs);
  process_path<0,1,1>( 3, ch0, ws, x1s,x2t, wss,Ts,sC, acc0,acc1, tid,wt,zs);
  process_path<1,0,1>( 4, ch0, ws, x1s,x2t, wss,Ts,sC, acc0,acc1, tid,wt,zs);
  process_path<1,2,1>( 5, ch0, ws, x1s,x2t, wss,Ts,sC, acc0,acc1, tid,wt,zs);
  process_path<2,1,1>( 6, ch0, ws, x1s,x2t, wss,Ts,sC, acc0,acc1, tid,wt,zs);
  process_path<0,2,2>( 7, ch0, ws, x1s,x2t, wss,Ts,sC, acc0,acc1, tid,wt,zs);
  process_path<1,1,2>( 8, ch0, ws, x1s,x2t, wss,Ts,sC, acc0,acc1, tid,wt,zs);
  process_path<2,0,2>( 9, ch0, ws, x1s,x2t, wss,Ts,sC, acc0,acc1, tid,wt,zs);
  process_path<2,2,2>(10, ch0, ws, x1s,x2t, wss,Ts,sC, acc0,acc1, tid,wt,zs);

  const float A0 = 0.01804219591217583f;   // sqrt(1/3072)
  const float A1 = 0.02706329386826371f;   // sqrt(3)/64
  const float A2 = 0.03493856214843422f;   // sqrt(5)/64

  float* o = g_part[half] + (size_t)(zbase + zs) * DIMF;
  int w0 = wt, w1 = wt + 16;
  o[w0] = A0 * acc0[0];
  o[w1] = A0 * acc1[0];
  #pragma unroll
  for (int k = 0; k < 3; ++k){
    o[32 + w0*3 + k] = A1 * acc0[1+k];
    o[32 + w1*3 + k] = A1 * acc1[1+k];
  }
  #pragma unroll
  for (int k = 0; k < 5; ++k){
    o[128 + w0*5 + k] = A2 * acc0[4+k];
    o[128 + w1*5 + k] = A2 * acc1[4+k];
  }
}

__global__ void reduce_kernel(float* __restrict__ out){
  int i = blockIdx.x * blockDim.x + threadIdx.x;
  float4 r = make_float4(0.f, 0.f, 0.f, 0.f);
  #pragma unroll
  for (int s = 0; s < UVS; ++s){
    float4 a = ((const float4*)g_part[s])[i];
    r.x += a.x; r.y += a.y; r.z += a.z; r.w += a.w;
  }
  ((float4*)out)[i] = r;
}

extern "C" void kernel_launch(void* const* d_in, const int* in_sizes, int n_in,
                              void* d_out, int out_size) {
  const float* x1 = (const float*)d_in[0];
  const float* x2 = (const float*)d_in[1];
  const float* ws = (const float*)d_in[2];
  float* out = (float*)d_out;
  (void)in_sizes; (void)n_in; (void)out_size;

  static float h_C[NPATH][125];
  compute_w3j_dense(h_C);
  cudaMemcpyToSymbolAsync(g_C, h_C, sizeof(h_C), 0, cudaMemcpyHostToDevice, 0);

  tp_kernel<<<(2048/BZ)*UVS, NT>>>(x1, x2, ws);
  reduce_kernel<<<(2048*DIMF/4)/256, 256>>>(out);
}